// round 14
// baseline (speedup 1.0000x reference)
#include <cuda_runtime.h>

// ChamferLoss: B=8, N=M=4096, C=3, fp32 in, scalar fp32 out.
// Exact NN via 2D (z,y) binning: counting sort on key = zbin*16 + ybin
// (64 z-bins x 16 y-bins). One WARP per 32 key-sorted sources. For each z-ring
// scan only the contiguous y-bin window covering every lane's current-best
// radius; expand rings outward with per-lane ballots. Radii only shrink and
// bin gap lower-bounds only grow -> all skip decisions provably safe -> exact.
// Objective: best = max_t (s.t - |t|^2/2);  d2 = |s|^2 - 2*best.

#define BATCH  8
#define NPTS   4096
#define BN     (BATCH * NPTS)

#define NZ     64
#define NY     16
#define NKEY   (NZ * NY)          // 1024 bins
#define ZLO    (-4.0f)
#define ZWZ    (8.0f / NZ)        // 0.125
#define ZINVZ  (NZ / 8.0f)        // 8
#define YLO    (-4.0f)
#define YW     (8.0f / NY)        // 0.5
#define YINV   (NY / 8.0f)        // 2

#define WPB         4
#define THREADS     (32 * WPB)
#define BANDS       128                    // 32-source bands per (dir, batch)
#define TOTAL_WARPS (2 * BATCH * BANDS)    // 2048
#define NN_BLOCKS   (TOTAL_WARPS / WPB)    // 512

// Sorted AoS: [cloud][batch][pos] = (x, y, z, -0.5*|p|^2), key-ascending.
__device__ float4 g_pts[2][BATCH][NPTS];
__device__ int    g_kstart[2][BATCH][NKEY + 1];
__device__ float  g_csum[TOTAL_WARPS];
__device__ int    g_count;  // statically 0; last warp resets for graph replay

// One block per (cloud, batch): 1024-bin histogram -> prefix -> scatter.
__global__ __launch_bounds__(1024)
void build_kernel(const float* __restrict__ f, const float* __restrict__ f_) {
    const int cloud = blockIdx.x >> 3;
    const int b     = blockIdx.x & 7;
    const float* pts = (cloud ? f_ : f) + (size_t)b * NPTS * 3;
    const int tid = threadIdx.x;

    __shared__ int cnt[NKEY], pre[NKEY], offs[NKEY];
    cnt[tid] = 0;
    __syncthreads();

    int mykey[4];
#pragma unroll
    for (int e = 0; e < 4; e++) {
        int i = tid + e * 1024;
        float y = pts[i * 3 + 1];
        float z = pts[i * 3 + 2];
        int zb = min(max((int)((z - ZLO) * ZINVZ), 0), NZ - 1);
        int yb = min(max((int)((y - YLO) * YINV),  0), NY - 1);
        mykey[e] = zb * NY + yb;
        atomicAdd(&cnt[mykey[e]], 1);
    }
    __syncthreads();

    pre[tid] = cnt[tid];
    __syncthreads();
    for (int s = 1; s < NKEY; s <<= 1) {     // Hillis-Steele inclusive scan
        int v = 0;
        if (tid >= s) v = pre[tid - s];
        __syncthreads();
        pre[tid] += v;
        __syncthreads();
    }
    {
        int st = pre[tid] - cnt[tid];        // exclusive start
        g_kstart[cloud][b][tid] = st;
        offs[tid] = st;
    }
    if (tid == 0) g_kstart[cloud][b][NKEY] = NPTS;
    __syncthreads();

#pragma unroll
    for (int e = 0; e < 4; e++) {
        int i = tid + e * 1024;
        float x = pts[i * 3 + 0], y = pts[i * 3 + 1], z = pts[i * 3 + 2];
        int pos = atomicAdd(&offs[mykey[e]], 1);  // within-bin order arbitrary:
        g_pts[cloud][b][pos] =                    // max over set is unchanged
            make_float4(x, y, z, -0.5f * (x * x + y * y + z * z));
    }
}

__device__ __forceinline__ float wrmin(float v) {
#pragma unroll
    for (int o = 16; o > 0; o >>= 1)
        v = fminf(v, __shfl_xor_sync(0xffffffffu, v, o));
    return v;
}
__device__ __forceinline__ float wrmax(float v) {
#pragma unroll
    for (int o = 16; o > 0; o >>= 1)
        v = fmaxf(v, __shfl_xor_sync(0xffffffffu, v, o));
    return v;
}

__global__ __launch_bounds__(THREADS)
void nn_kernel(float* __restrict__ out) {
    const int lane = threadIdx.x & 31;
    const int wid  = threadIdx.x >> 5;
    const int wgid = blockIdx.x * WPB + wid;     // [0, 2048)
    const int dir  = wgid >> 10;
    const int b    = (wgid >> 7) & 7;
    const int band = wgid & (BANDS - 1);

    const float4* tp  = g_pts[1 - dir][b];
    const int*    ts2 = g_kstart[1 - dir][b];

    const float4 s = g_pts[dir][b][band * 32 + lane];
    float bA = -3.402823466e+38f, bB = -3.402823466e+38f;

    // Direct warp-uniform broadcast scan of positions [p0, p1); 2-way ILP.
    auto seg = [&](int p0, int p1) {
        int p = p0;
        for (; p + 1 < p1; p += 2) {
            float4 q0 = tp[p];                   // uniform addr -> L1 broadcast
            float4 q1 = tp[p + 1];
            float v0 = fmaf(s.x, q0.x, q0.w);
            v0 = fmaf(s.y, q0.y, v0);
            v0 = fmaf(s.z, q0.z, v0);
            bA = fmaxf(bA, v0);
            float v1 = fmaf(s.x, q1.x, q1.w);
            v1 = fmaf(s.y, q1.y, v1);
            v1 = fmaf(s.z, q1.z, v1);
            bB = fmaxf(bB, v1);
        }
        if (p < p1) {
            float4 q = tp[p];
            float v = fmaf(s.x, q.x, q.w);
            v = fmaf(s.y, q.y, v);
            v = fmaf(s.z, q.z, v);
            bA = fmaxf(bA, v);
        }
    };

    // Scan ring zr restricted to the warp's current y-reach window.
    // Window [wrmin(y_i - r_i), wrmax(y_i + r_i)] covers every lane; skipped
    // y-bins have |dy| >= r_i(now) >= r_i(final) for all lanes -> exact.
    auto scan_ring = [&](int zr) {
        float d2 = fmaxf(-2.0f * (s.w + fmaxf(bA, bB)), 0.0f);
        float r = __fsqrt_rn(d2);               // inf-safe
        float wlo = wrmin(s.y - r);
        float whi = wrmax(s.y + r);
        int yb0 = (int)fmaxf(0.0f, fminf((float)(NY - 1),
                      floorf((wlo - YLO) * YINV)));
        int yb1 = (int)fmaxf(0.0f, fminf((float)(NY - 1),
                      floorf((whi - YLO) * YINV)));
        seg(ts2[zr * NY + yb0], ts2[zr * NY + yb1 + 1]);
    };

    int zb = min(max((int)((s.z - ZLO) * ZINVZ), 0), NZ - 1);
    const int zmin = __shfl_sync(0xffffffffu, zb, 0);   // key-ascending order
    const int zmax = __shfl_sync(0xffffffffu, zb, 31);

    // Phase A: own ring(s), fixed +-1-ybin window around the warp's y-span.
    // Cheap finite initial bound; coverage gaps are re-validated below.
    {
        float wlo = wrmin(s.y) - YW;
        float whi = wrmax(s.y) + YW;
        int yb0 = (int)fmaxf(0.0f, fminf((float)(NY - 1),
                      floorf((wlo - YLO) * YINV)));
        int yb1 = (int)fmaxf(0.0f, fminf((float)(NY - 1),
                      floorf((whi - YLO) * YINV)));
        for (int zr = zmin; zr <= zmax; zr++)
            seg(ts2[zr * NY + yb0], ts2[zr * NY + yb1 + 1]);
    }

    // Phase B: re-scan own rings with proper r-windows (validates phase-A
    // coverage; duplicate candidates are harmless for a max), then expand
    // outward ring-by-ring with per-lane reachability ballots.
    for (int zr = zmin; zr <= zmax; zr++) scan_ring(zr);

    int zlo = zmin, zhi = zmax;
    bool la = (zlo > 0), ra = (zhi < NZ - 1);
    while (la || ra) {
        if (la) {
            float d2 = fmaxf(-2.0f * (s.w + fmaxf(bA, bB)), 0.0f);
            float dz = s.z - (ZLO + (float)zlo * ZWZ);   // lb for ring zlo-1
            if (__any_sync(0xffffffffu, dz * dz < d2)) {
                zlo--; scan_ring(zlo); la = (zlo > 0);
            } else la = false;
        }
        if (ra) {
            float d2 = fmaxf(-2.0f * (s.w + fmaxf(bA, bB)), 0.0f);
            float dz = (ZLO + (float)(zhi + 1) * ZWZ) - s.z;  // lb for zhi+1
            if (__any_sync(0xffffffffu, dz * dz < d2)) {
                zhi++; scan_ring(zhi); ra = (zhi < NZ - 1);
            } else ra = false;
        }
    }

    // Per-lane term = |s|^2 - 2*best; deterministic warp shuffle tree.
    float term = -2.0f * (s.w + fmaxf(bA, bB));
#pragma unroll
    for (int off = 16; off > 0; off >>= 1)
        term += __shfl_down_sync(0xffffffffu, term, off);

    unsigned last = 0;
    if (lane == 0) {
        g_csum[wgid] = term;
        __threadfence();
        last = (atomicAdd(&g_count, 1) == TOTAL_WARPS - 1) ? 1u : 0u;
    }
    last = __shfl_sync(0xffffffffu, last, 0);

    if (last) {
        __threadfence();  // acquire: all g_csum writes visible
        float acc = 0.0f;
#pragma unroll
        for (int kk = 0; kk < TOTAL_WARPS / 32; kk++)   // 64 loads, fixed order
            acc += g_csum[lane + kk * 32];
#pragma unroll
        for (int off = 16; off > 0; off >>= 1)
            acc += __shfl_down_sync(0xffffffffu, acc, off);
        if (lane == 0) {
            out[0] = acc * (1.0f / (float)BN);
            g_count = 0;  // reset for next graph replay
        }
    }
}

extern "C" void kernel_launch(void* const* d_in, const int* in_sizes, int n_in,
                              void* d_out, int out_size) {
    const float* f  = (const float*)d_in[0];
    const float* f_ = (const float*)d_in[1];
    float* out = (float*)d_out;

    build_kernel<<<16, 1024>>>(f, f_);        // 2 clouds x 8 batches
    nn_kernel<<<NN_BLOCKS, THREADS>>>(out);   // 512 blocks x 128 threads
}

// round 15
// speedup vs baseline: 2.3577x; 2.3577x over previous
#include <cuda_runtime.h>

// ChamferLoss: B=8, N=M=4096, C=3, fp32 in, scalar fp32 out.
// Exact NN via 2D (z,y) counting sort: key = zbin(32)*16 + ybin(16).
// One WARP per 32 key-sorted sources; per z-ring scan only the contiguous
// y-bin window covering every lane's current-best radius (shared-tile
// broadcast engine); expand rings outward with per-lane ballots. Radii only
// shrink, bin-gap lower bounds only grow -> skips provably safe -> exact.
// Objective: best = max_t (s.t - |t|^2/2);  d2 = |s|^2 - 2*best.

#define BATCH  8
#define NPTS   4096
#define BN     (BATCH * NPTS)

#define NZ     32
#define NY     16
#define NKEY   (NZ * NY)          // 512 bins
#define ZLO    (-4.0f)
#define ZWZ    0.25f
#define ZINVZ  4.0f
#define YLO    (-4.0f)
#define YW     0.5f
#define YINV   2.0f

#define WPB         4
#define THREADS     (32 * WPB)
#define BANDS       128                    // 32-source bands per (dir, batch)
#define TOTAL_WARPS (2 * BATCH * BANDS)    // 2048
#define NN_BLOCKS   (TOTAL_WARPS / WPB)    // 512

// Sorted AoS: [cloud][batch][pos] = (x, y, z, -0.5*|p|^2), key-ascending.
__device__ float4 g_pts[2][BATCH][NPTS];
__device__ int    g_kstart[2][BATCH][NKEY + 1];
__device__ float  g_csum[TOTAL_WARPS];
__device__ int    g_count;  // statically 0; last warp resets for graph replay

// One block per (cloud, batch): histogram -> prefix -> scatter.
__global__ __launch_bounds__(1024)
void build_kernel(const float* __restrict__ f, const float* __restrict__ f_) {
    const int cloud = blockIdx.x >> 3;
    const int b     = blockIdx.x & 7;
    const float* pts = (cloud ? f_ : f) + (size_t)b * NPTS * 3;
    const int tid = threadIdx.x;

    __shared__ int cnt[NKEY], pre[NKEY], offs[NKEY];
    if (tid < NKEY) cnt[tid] = 0;
    __syncthreads();

    int mykey[4];
#pragma unroll
    for (int e = 0; e < 4; e++) {
        int i = tid + e * 1024;
        float y = pts[i * 3 + 1];
        float z = pts[i * 3 + 2];
        int zb = min(max((int)((z - ZLO) * ZINVZ), 0), NZ - 1);
        int yb = min(max((int)((y - YLO) * YINV),  0), NY - 1);
        mykey[e] = zb * NY + yb;
        atomicAdd(&cnt[mykey[e]], 1);
    }
    __syncthreads();

    if (tid < NKEY) pre[tid] = cnt[tid];
    __syncthreads();
    for (int s = 1; s < NKEY; s <<= 1) {     // Hillis-Steele inclusive scan
        int v = 0;
        if (tid < NKEY && tid >= s) v = pre[tid - s];
        __syncthreads();
        if (tid < NKEY) pre[tid] += v;
        __syncthreads();
    }
    if (tid < NKEY) {
        int st = pre[tid] - cnt[tid];        // exclusive start
        g_kstart[cloud][b][tid] = st;
        offs[tid] = st;
    }
    if (tid == 0) g_kstart[cloud][b][NKEY] = NPTS;
    __syncthreads();

#pragma unroll
    for (int e = 0; e < 4; e++) {
        int i = tid + e * 1024;
        float x = pts[i * 3 + 0], y = pts[i * 3 + 1], z = pts[i * 3 + 2];
        int pos = atomicAdd(&offs[mykey[e]], 1);  // within-bin order arbitrary:
        g_pts[cloud][b][pos] =                    // max over set is unchanged
            make_float4(x, y, z, -0.5f * (x * x + y * y + z * z));
    }
}

__device__ __forceinline__ float wrminf(float v) {
#pragma unroll
    for (int o = 16; o > 0; o >>= 1)
        v = fminf(v, __shfl_xor_sync(0xffffffffu, v, o));
    return v;
}
__device__ __forceinline__ float wrmaxf(float v) {
#pragma unroll
    for (int o = 16; o > 0; o >>= 1)
        v = fmaxf(v, __shfl_xor_sync(0xffffffffu, v, o));
    return v;
}

__global__ __launch_bounds__(THREADS)
void nn_kernel(float* __restrict__ out) {
    const int lane = threadIdx.x & 31;
    const int wid  = threadIdx.x >> 5;
    const int wgid = blockIdx.x * WPB + wid;     // [0, 2048)
    const int dir  = wgid >> 10;
    const int b    = (wgid >> 7) & 7;
    const int band = wgid & (BANDS - 1);

    const float4* tp  = g_pts[1 - dir][b];
    const int*    ts2 = g_kstart[1 - dir][b];

    __shared__ float4 tile[WPB][32];             // per-warp private tile
    float4* sh = tile[wid];

    const float4 s = g_pts[dir][b][band * 32 + lane];
    float bA = -3.402823466e+38f, bB = -3.402823466e+38f;

    // R12 tile engine: contiguous scan of [p0, p1), broadcast LDS, 2-way ILP.
    auto scan = [&](int p0, int p1) {
        for (int base = p0; base < p1; base += 32) {
            int p = base + lane;
            float4 v = (p < p1) ? tp[p]
                                : make_float4(0.f, 0.f, 0.f, -3.402823466e+38f);
            __syncwarp();
            sh[lane] = v;
            __syncwarp();
#pragma unroll
            for (int j = 0; j < 32; j += 2) {
                float4 q0 = sh[j];
                float v0 = fmaf(s.x, q0.x, q0.w);
                v0 = fmaf(s.y, q0.y, v0);
                v0 = fmaf(s.z, q0.z, v0);
                bA = fmaxf(bA, v0);
                float4 q1 = sh[j + 1];
                float v1 = fmaf(s.x, q1.x, q1.w);
                v1 = fmaf(s.y, q1.y, v1);
                v1 = fmaf(s.z, q1.z, v1);
                bB = fmaxf(bB, v1);
            }
        }
    };

    // Ring zr with the warp's current y-reach window. Skipped y-bins satisfy
    // |y_t - y_i| >= r_i(now) >= r_i(final) for every lane -> exact.
    auto scan_ring = [&](int zr) {
        float d2 = fmaxf(-2.0f * (s.w + fmaxf(bA, bB)), 0.0f);
        float r = __fsqrt_rn(d2);
        float wlo = wrminf(s.y - r);
        float whi = wrmaxf(s.y + r);
        int yb0 = (int)fmaxf(0.0f, fminf((float)(NY - 1),
                      floorf((wlo - YLO) * YINV)));
        int yb1 = (int)fmaxf(0.0f, fminf((float)(NY - 1),
                      floorf((whi - YLO) * YINV)));
        scan(ts2[zr * NY + yb0], ts2[zr * NY + yb1 + 1]);
    };

    const int zb = min(max((int)((s.z - ZLO) * ZINVZ), 0), NZ - 1);
    const int zmin = __shfl_sync(0xffffffffu, zb, 0);   // key order: zb ascends
    const int zmax = __shfl_sync(0xffffffffu, zb, 31);

    // Phase A: own rings, warp y-span +-1 ybin -> cheap finite initial bound.
    {
        float wlo = wrminf(s.y) - YW;
        float whi = wrmaxf(s.y) + YW;
        int yb0 = (int)fmaxf(0.0f, fminf((float)(NY - 1),
                      floorf((wlo - YLO) * YINV)));
        int yb1 = (int)fmaxf(0.0f, fminf((float)(NY - 1),
                      floorf((whi - YLO) * YINV)));
        for (int zr = zmin; zr <= zmax; zr++)
            scan(ts2[zr * NY + yb0], ts2[zr * NY + yb1 + 1]);
    }

    // Rare fallback: if any lane's bound is still terrible (empty/thin phase-A
    // windows), seed with 64 contiguous sorted targets near the warp's key.
    {
        float d2 = fmaxf(-2.0f * (s.w + fmaxf(bA, bB)), 0.0f);
        if (__any_sync(0xffffffffu, d2 > 4.0f)) {
            int pc = ts2[zmin * NY];
            int p0 = max(0, min(NPTS - 64, pc - 32));
            scan(p0, p0 + 64);
        }
    }

    // Phase B: own rings with proper r-windows (covers any phase-A gap;
    // duplicate candidates are harmless for a max), then adaptive expansion.
    for (int zr = zmin; zr <= zmax; zr++) scan_ring(zr);

    int zlo = zmin, zhi = zmax;
    bool la = (zlo > 0), ra = (zhi < NZ - 1);
    while (la || ra) {
        if (la) {
            float d2 = fmaxf(-2.0f * (s.w + fmaxf(bA, bB)), 0.0f);
            float dz = s.z - (ZLO + (float)zlo * ZWZ);   // lb for ring zlo-1
            if (__any_sync(0xffffffffu, dz * dz < d2)) {
                zlo--; scan_ring(zlo); la = (zlo > 0);
            } else la = false;
        }
        if (ra) {
            float d2 = fmaxf(-2.0f * (s.w + fmaxf(bA, bB)), 0.0f);
            float dz = (ZLO + (float)(zhi + 1) * ZWZ) - s.z;  // lb for zhi+1
            if (__any_sync(0xffffffffu, dz * dz < d2)) {
                zhi++; scan_ring(zhi); ra = (zhi < NZ - 1);
            } else ra = false;
        }
    }

    // Per-lane term = |s|^2 - 2*best; deterministic warp shuffle tree.
    float term = -2.0f * (s.w + fmaxf(bA, bB));
#pragma unroll
    for (int off = 16; off > 0; off >>= 1)
        term += __shfl_down_sync(0xffffffffu, term, off);

    unsigned last = 0;
    if (lane == 0) {
        g_csum[wgid] = term;
        __threadfence();
        last = (atomicAdd(&g_count, 1) == TOTAL_WARPS - 1) ? 1u : 0u;
    }
    last = __shfl_sync(0xffffffffu, last, 0);

    if (last) {
        __threadfence();  // acquire: all g_csum writes visible
        float acc = 0.0f;
#pragma unroll
        for (int kk = 0; kk < TOTAL_WARPS / 32; kk++)   // 64 loads, fixed order
            acc += g_csum[lane + kk * 32];
#pragma unroll
        for (int off = 16; off > 0; off >>= 1)
            acc += __shfl_down_sync(0xffffffffu, acc, off);
        if (lane == 0) {
            out[0] = acc * (1.0f / (float)BN);
            g_count = 0;  // reset for next graph replay
        }
    }
}

extern "C" void kernel_launch(void* const* d_in, const int* in_sizes, int n_in,
                              void* d_out, int out_size) {
    const float* f  = (const float*)d_in[0];
    const float* f_ = (const float*)d_in[1];
    float* out = (float*)d_out;

    build_kernel<<<16, 1024>>>(f, f_);        // 2 clouds x 8 batches
    nn_kernel<<<NN_BLOCKS, THREADS>>>(out);   // 512 blocks x 128 threads
}

// round 16
// speedup vs baseline: 2.7812x; 1.1796x over previous
#include <cuda_runtime.h>

// ChamferLoss: B=8, N=M=4096, C=3, fp32 in, scalar fp32 out.
// Exact NN via 2D (z,y) counting sort: key = zbin(32)*16 + ybin(16).
// One WARP per 8 key-sorted sources held in uniform registers (shfl
// broadcast); candidates distributed across lanes (coalesced LDG.128).
// Per z-ring scan only the y-bin window covering every source's CURRENT
// radius; expand rings outward while any source can reach them. All bounds
// warp-uniform (post-reduce) -> uniform control, no ballots. Radii only
// shrink, bin-gap lower bounds only grow -> skips provably safe -> exact.
// Objective: best = max_t (s.t - |t|^2/2);  d2 = |s|^2 - 2*best.

#define BATCH  8
#define NPTS   4096
#define BN     (BATCH * NPTS)

#define NZ     32
#define NY     16
#define NKEY   (NZ * NY)          // 512 bins
#define ZLO    (-4.0f)
#define ZWZ    0.25f
#define ZINVZ  4.0f
#define YLO    (-4.0f)
#define YW     0.5f
#define YINV   2.0f

#define GRP         8                       // sources per warp
#define NGRP        (NPTS / GRP)            // 512 groups per (dir, batch)
#define TOTAL_WARPS (2 * BATCH * NGRP)      // 8192
#define WPB         8
#define THREADS     (32 * WPB)              // 256
#define NN_BLOCKS   (TOTAL_WARPS / WPB)     // 1024

#define FULLM 0xffffffffu
#define NEGBIG (-3.402823466e+38f)

// Sorted AoS: [cloud][batch][pos] = (x, y, z, -0.5*|p|^2), key-ascending.
__device__ float4 g_pts[2][BATCH][NPTS];
__device__ int    g_kstart[2][BATCH][NKEY + 1];
__device__ float  g_csum[TOTAL_WARPS];
__device__ int    g_count;  // statically 0; last warp resets for graph replay

// One block per (cloud, batch): histogram -> prefix -> scatter.
__global__ __launch_bounds__(1024)
void build_kernel(const float* __restrict__ f, const float* __restrict__ f_) {
    const int cloud = blockIdx.x >> 3;
    const int b     = blockIdx.x & 7;
    const float* pts = (cloud ? f_ : f) + (size_t)b * NPTS * 3;
    const int tid = threadIdx.x;

    __shared__ int cnt[NKEY], pre[NKEY], offs[NKEY];
    if (tid < NKEY) cnt[tid] = 0;
    __syncthreads();

    int mykey[4];
#pragma unroll
    for (int e = 0; e < 4; e++) {
        int i = tid + e * 1024;
        float y = pts[i * 3 + 1];
        float z = pts[i * 3 + 2];
        int zb = min(max((int)((z - ZLO) * ZINVZ), 0), NZ - 1);
        int yb = min(max((int)((y - YLO) * YINV),  0), NY - 1);
        mykey[e] = zb * NY + yb;
        atomicAdd(&cnt[mykey[e]], 1);
    }
    __syncthreads();

    if (tid < NKEY) pre[tid] = cnt[tid];
    __syncthreads();
    for (int s = 1; s < NKEY; s <<= 1) {     // Hillis-Steele inclusive scan
        int v = 0;
        if (tid < NKEY && tid >= s) v = pre[tid - s];
        __syncthreads();
        if (tid < NKEY) pre[tid] += v;
        __syncthreads();
    }
    if (tid < NKEY) {
        int st = pre[tid] - cnt[tid];        // exclusive start
        g_kstart[cloud][b][tid] = st;
        offs[tid] = st;
    }
    if (tid == 0) g_kstart[cloud][b][NKEY] = NPTS;
    __syncthreads();

#pragma unroll
    for (int e = 0; e < 4; e++) {
        int i = tid + e * 1024;
        float x = pts[i * 3 + 0], y = pts[i * 3 + 1], z = pts[i * 3 + 2];
        int pos = atomicAdd(&offs[mykey[e]], 1);  // within-bin order arbitrary:
        g_pts[cloud][b][pos] =                    // max over set is unchanged
            make_float4(x, y, z, -0.5f * (x * x + y * y + z * z));
    }
}

__global__ __launch_bounds__(THREADS)
void nn_kernel(float* __restrict__ out) {
    const int lane = threadIdx.x & 31;
    const int wid  = threadIdx.x >> 5;
    const int wg   = blockIdx.x * WPB + wid;     // [0, 8192)
    const int dir  = wg >> 12;
    const int b    = (wg >> 9) & 7;
    const int grp  = wg & (NGRP - 1);

    const float4* sp = g_pts[dir][b];
    const float4* tp = g_pts[1 - dir][b];
    const int*    ks = g_kstart[1 - dir][b];

    // Broadcast 8 sources into uniform registers.
    const float4 sl = sp[grp * GRP + (lane & (GRP - 1))];
    float sx[GRP], sy[GRP], sz[GRP], sw[GRP], mx[GRP];
#pragma unroll
    for (int k = 0; k < GRP; k++) {
        sx[k] = __shfl_sync(FULLM, sl.x, k);
        sy[k] = __shfl_sync(FULLM, sl.y, k);
        sz[k] = __shfl_sync(FULLM, sl.z, k);
        sw[k] = __shfl_sync(FULLM, sl.w, k);
        mx[k] = NEGBIG;
    }

    // Candidates across lanes: coalesced LDG.128; 8x4 independent ops/iter.
    auto scan = [&](int p0, int p1) {
        for (int bs = p0; bs < p1; bs += 32) {
            int p = bs + lane;
            float4 q = (p < p1) ? tp[p] : make_float4(0.f, 0.f, 0.f, NEGBIG);
#pragma unroll
            for (int k = 0; k < GRP; k++) {
                float v = fmaf(sx[k], q.x, q.w);
                v = fmaf(sy[k], q.y, v);
                v = fmaf(sz[k], q.z, v);
                mx[k] = fmaxf(mx[k], v);
            }
        }
    };
    // Make mx warp-uniform (full max per source).
    auto reduce = [&]() {
#pragma unroll
        for (int k = 0; k < GRP; k++) {
#pragma unroll
            for (int o = 16; o > 0; o >>= 1)
                mx[k] = fmaxf(mx[k], __shfl_xor_sync(FULLM, mx[k], o));
        }
    };
    auto d2k = [&](int k) {                      // uniform after reduce
        return fmaxf(-2.0f * (sw[k] + mx[k]), 0.0f);
    };

    // Ring scan with per-source current-radius y-window. Skipped y-bins have
    // |dy| >= r_k(now) >= r_k(final) for every source -> exact.
    auto scan_ring = [&](int zr) {
        float wlo = 1e30f, whi = -1e30f;
#pragma unroll
        for (int k = 0; k < GRP; k++) {
            float r = __fsqrt_rn(d2k(k));
            wlo = fminf(wlo, sy[k] - r);
            whi = fmaxf(whi, sy[k] + r);
        }
        int y0 = (int)fmaxf(0.0f, fminf((float)(NY - 1),
                     floorf((wlo - YLO) * YINV)));
        int y1 = (int)fmaxf(0.0f, fminf((float)(NY - 1),
                     floorf((whi - YLO) * YINV)));
        scan(ks[zr * NY + y0], ks[zr * NY + y1 + 1]);
        reduce();
    };

    // Group bin span (keys ascend with position: source 0 min, source 7 max).
    const int zmin = min(max((int)((sz[0] - ZLO) * ZINVZ), 0), NZ - 1);
    const int zmax = min(max((int)((sz[GRP - 1] - ZLO) * ZINVZ), 0), NZ - 1);

    // Phase A: own rings, group y-span +- 1 ybin -> cheap initial bound.
    {
        float ymin = sy[0], ymax = sy[0];
#pragma unroll
        for (int k = 1; k < GRP; k++) {
            ymin = fminf(ymin, sy[k]);
            ymax = fmaxf(ymax, sy[k]);
        }
        int a0 = (int)fmaxf(0.0f, fminf((float)(NY - 1),
                     floorf((ymin - YW - YLO) * YINV)));
        int a1 = (int)fmaxf(0.0f, fminf((float)(NY - 1),
                     floorf((ymax + YW - YLO) * YINV)));
        for (int zr = zmin; zr <= zmax; zr++)
            scan(ks[zr * NY + a0], ks[zr * NY + a1 + 1]);
        reduce();
    }

    // Rare fallback: weak bound (thin/empty windows) -> seed with 64
    // contiguous sorted targets near the group's key position.
    {
        float dmax = 0.0f;
#pragma unroll
        for (int k = 0; k < GRP; k++) dmax = fmaxf(dmax, d2k(k));
        if (dmax > 4.0f) {
            int pc = ks[zmin * NY];
            int p0 = max(0, min(NPTS - 64, pc - 32));
            scan(p0, p0 + 64);
            reduce();
        }
    }

    // Phase B: own rings with proper r-windows (covers phase-A gaps;
    // duplicates harmless for max), then adaptive ring expansion outward.
    for (int zr = zmin; zr <= zmax; zr++) scan_ring(zr);

    int zlo = zmin, zhi = zmax;
    bool la = (zlo > 0), ra = (zhi < NZ - 1);
    while (la || ra) {
        if (la) {                       // ring zlo-1: all z <= ZLO + zlo*ZWZ
            bool go = false;
#pragma unroll
            for (int k = 0; k < GRP; k++) {
                float dz = fmaxf(sz[k] - (ZLO + (float)zlo * ZWZ), 0.0f);
                go |= (dz * dz < d2k(k));
            }
            if (go) { zlo--; scan_ring(zlo); la = (zlo > 0); }
            else la = false;
        }
        if (ra) {                       // ring zhi+1: all z >= ZLO+(zhi+1)*ZWZ
            bool go = false;
#pragma unroll
            for (int k = 0; k < GRP; k++) {
                float dz = fmaxf((ZLO + (float)(zhi + 1) * ZWZ) - sz[k], 0.0f);
                go |= (dz * dz < d2k(k));
            }
            if (go) { zhi++; scan_ring(zhi); ra = (zhi < NZ - 1); }
            else la = la, ra = false;
        }
    }

    // Group term (uniform): sum_k (|s_k|^2 - 2*best_k).
    float term = 0.0f;
#pragma unroll
    for (int k = 0; k < GRP; k++) term += -2.0f * (sw[k] + mx[k]);

    unsigned last = 0;
    if (lane == 0) {
        g_csum[wg] = term;
        __threadfence();
        last = (atomicAdd(&g_count, 1) == TOTAL_WARPS - 1) ? 1u : 0u;
    }
    last = __shfl_sync(FULLM, last, 0);

    if (last) {
        __threadfence();  // acquire: all g_csum writes visible
        float acc = 0.0f;
#pragma unroll 8
        for (int kk = 0; kk < TOTAL_WARPS / 32; kk++)   // 256, fixed order
            acc += g_csum[lane + kk * 32];
#pragma unroll
        for (int off = 16; off > 0; off >>= 1)
            acc += __shfl_down_sync(FULLM, acc, off);
        if (lane == 0) {
            out[0] = acc * (1.0f / (float)BN);
            g_count = 0;  // reset for next graph replay
        }
    }
}

extern "C" void kernel_launch(void* const* d_in, const int* in_sizes, int n_in,
                              void* d_out, int out_size) {
    const float* f  = (const float*)d_in[0];
    const float* f_ = (const float*)d_in[1];
    float* out = (float*)d_out;

    build_kernel<<<16, 1024>>>(f, f_);        // 2 clouds x 8 batches
    nn_kernel<<<NN_BLOCKS, THREADS>>>(out);   // 1024 blocks x 256 threads
}

// round 17
// speedup vs baseline: 2.9594x; 1.0641x over previous
#include <cuda_runtime.h>

// ChamferLoss: B=8, N=M=4096, C=3, fp32 in, scalar fp32 out.
// Exact NN via 2D (z,y) counting sort: key = zbin(32)*16 + ybin(16).
// One WARP per 8 key-sorted sources in uniform registers; candidates across
// lanes (coalesced LDG.128). Bounds are checkpoint-reduced (2 full reduces
// total); ring scans use fixed-bound CHORD windows: source k reaches ring at
// z-gap dz only within |dy| <= sqrt(d2_k - dz^2). Frozen bounds are upper
// bounds of final ones and gap lower-bounds grow outward -> skips safe, empty-
// window stop monotone -> exact.
// Objective: best = max_t (s.t - |t|^2/2);  d2 = |s|^2 - 2*best.

#define BATCH  8
#define NPTS   4096
#define BN     (BATCH * NPTS)

#define NZ     32
#define NY     16
#define NKEY   (NZ * NY)          // 512 bins
#define ZLO    (-4.0f)
#define ZWZ    0.25f
#define ZINVZ  4.0f
#define YLO    (-4.0f)
#define YW     0.5f
#define YINV   2.0f

#define GRP         8                       // sources per warp
#define NGRP        (NPTS / GRP)            // 512 groups per (dir, batch)
#define TOTAL_WARPS (2 * BATCH * NGRP)      // 8192
#define WPB         8
#define THREADS     (32 * WPB)              // 256
#define NN_BLOCKS   (TOTAL_WARPS / WPB)     // 1024

#define FULLM 0xffffffffu
#define NEGBIG (-3.402823466e+38f)

// Sorted AoS: [cloud][batch][pos] = (x, y, z, -0.5*|p|^2), key-ascending.
__device__ float4 g_pts[2][BATCH][NPTS];
__device__ int    g_kstart[2][BATCH][NKEY + 1];
__device__ float  g_csum[TOTAL_WARPS];
__device__ int    g_count;  // statically 0; last warp resets for graph replay

// One block per (cloud, batch): histogram -> prefix -> scatter.
__global__ __launch_bounds__(1024)
void build_kernel(const float* __restrict__ f, const float* __restrict__ f_) {
    const int cloud = blockIdx.x >> 3;
    const int b     = blockIdx.x & 7;
    const float* pts = (cloud ? f_ : f) + (size_t)b * NPTS * 3;
    const int tid = threadIdx.x;

    __shared__ int cnt[NKEY], pre[NKEY], offs[NKEY];
    if (tid < NKEY) cnt[tid] = 0;
    __syncthreads();

    int mykey[4];
#pragma unroll
    for (int e = 0; e < 4; e++) {
        int i = tid + e * 1024;
        float y = pts[i * 3 + 1];
        float z = pts[i * 3 + 2];
        int zb = min(max((int)((z - ZLO) * ZINVZ), 0), NZ - 1);
        int yb = min(max((int)((y - YLO) * YINV),  0), NY - 1);
        mykey[e] = zb * NY + yb;
        atomicAdd(&cnt[mykey[e]], 1);
    }
    __syncthreads();

    if (tid < NKEY) pre[tid] = cnt[tid];
    __syncthreads();
    for (int s = 1; s < NKEY; s <<= 1) {     // Hillis-Steele inclusive scan
        int v = 0;
        if (tid < NKEY && tid >= s) v = pre[tid - s];
        __syncthreads();
        if (tid < NKEY) pre[tid] += v;
        __syncthreads();
    }
    if (tid < NKEY) {
        int st = pre[tid] - cnt[tid];        // exclusive start
        g_kstart[cloud][b][tid] = st;
        offs[tid] = st;
    }
    if (tid == 0) g_kstart[cloud][b][NKEY] = NPTS;
    __syncthreads();

#pragma unroll
    for (int e = 0; e < 4; e++) {
        int i = tid + e * 1024;
        float x = pts[i * 3 + 0], y = pts[i * 3 + 1], z = pts[i * 3 + 2];
        int pos = atomicAdd(&offs[mykey[e]], 1);  // within-bin order arbitrary:
        g_pts[cloud][b][pos] =                    // max over set is unchanged
            make_float4(x, y, z, -0.5f * (x * x + y * y + z * z));
    }
}

__global__ __launch_bounds__(THREADS)
void nn_kernel(float* __restrict__ out) {
    const int lane = threadIdx.x & 31;
    const int wid  = threadIdx.x >> 5;
    const int wg   = blockIdx.x * WPB + wid;     // [0, 8192)
    const int dir  = wg >> 12;
    const int b    = (wg >> 9) & 7;
    const int grp  = wg & (NGRP - 1);

    const float4* sp = g_pts[dir][b];
    const float4* tp = g_pts[1 - dir][b];
    const int*    ks = g_kstart[1 - dir][b];

    // Broadcast 8 sources into uniform registers.
    const float4 sl = sp[grp * GRP + (lane & (GRP - 1))];
    float sx[GRP], sy[GRP], sz[GRP], sw[GRP], mx[GRP], d2u[GRP];
#pragma unroll
    for (int k = 0; k < GRP; k++) {
        sx[k] = __shfl_sync(FULLM, sl.x, k);
        sy[k] = __shfl_sync(FULLM, sl.y, k);
        sz[k] = __shfl_sync(FULLM, sl.z, k);
        sw[k] = __shfl_sync(FULLM, sl.w, k);
        mx[k] = NEGBIG;
    }

    // Candidates across lanes: coalesced LDG.128; 32 independent ops/iter.
    auto scan = [&](int p0, int p1) {
        for (int bs = p0; bs < p1; bs += 32) {
            int p = bs + lane;
            float4 q = (p < p1) ? tp[p] : make_float4(0.f, 0.f, 0.f, NEGBIG);
#pragma unroll
            for (int k = 0; k < GRP; k++) {
                float v = fmaf(sx[k], q.x, q.w);
                v = fmaf(sy[k], q.y, v);
                v = fmaf(sz[k], q.z, v);
                mx[k] = fmaxf(mx[k], v);
            }
        }
    };
    // Checkpoint: full-reduce mx, refresh uniform d2 bounds.
    auto checkpoint = [&]() {
#pragma unroll
        for (int k = 0; k < GRP; k++) {
#pragma unroll
            for (int o = 16; o > 0; o >>= 1)
                mx[k] = fmaxf(mx[k], __shfl_xor_sync(FULLM, mx[k], o));
            d2u[k] = fmaxf(-2.0f * (sw[k] + mx[k]), 0.0f);
        }
    };

    // Fixed-bound chord-window ring scan. Returns false iff no source can
    // reach ring zr (then no farther ring on that side can either).
    auto scan_ring = [&](int zr) -> bool {
        const float elo = ZLO + (float)zr * ZWZ;
        const float ehi = elo + ZWZ;
        float wlo = 1e30f, whi = -1e30f;
#pragma unroll
        for (int k = 0; k < GRP; k++) {
            float dz = fmaxf(fmaxf(elo - sz[k], sz[k] - ehi), 0.0f);
            float rem = fmaf(-dz, dz, d2u[k]);           // d2 - dz^2
            if (rem > 0.0f) {
                float ry = __fsqrt_rn(rem);
                wlo = fminf(wlo, sy[k] - ry);
                whi = fmaxf(whi, sy[k] + ry);
            }
        }
        if (whi < wlo) return false;
        int y0 = (int)fmaxf(0.0f, fminf((float)(NY - 1),
                     floorf((wlo - YLO) * YINV)));
        int y1 = (int)fmaxf(0.0f, fminf((float)(NY - 1),
                     floorf((whi - YLO) * YINV)));
        scan(ks[zr * NY + y0], ks[zr * NY + y1 + 1]);
        return true;
    };

    // Group z-ring span (keys ascend with position).
    const int zmin = min(max((int)((sz[0] - ZLO) * ZINVZ), 0), NZ - 1);
    const int zmax = min(max((int)((sz[GRP - 1] - ZLO) * ZINVZ), 0), NZ - 1);

    // Phase A: own rings, group y-span +-1 ybin -> cheap finite bound.
    {
        float ymin = sy[0], ymax = sy[0];
#pragma unroll
        for (int k = 1; k < GRP; k++) {
            ymin = fminf(ymin, sy[k]);
            ymax = fmaxf(ymax, sy[k]);
        }
        int a0 = (int)fmaxf(0.0f, fminf((float)(NY - 1),
                     floorf((ymin - YW - YLO) * YINV)));
        int a1 = (int)fmaxf(0.0f, fminf((float)(NY - 1),
                     floorf((ymax + YW - YLO) * YINV)));
        for (int zr = zmin; zr <= zmax; zr++)
            scan(ks[zr * NY + a0], ks[zr * NY + a1 + 1]);
        checkpoint();
    }

    // Rare fallback: weak bound -> seed with 64 contiguous sorted targets.
    {
        float dmax = 0.0f;
#pragma unroll
        for (int k = 0; k < GRP; k++) dmax = fmaxf(dmax, d2u[k]);
        if (dmax > 4.0f) {
            int pc = ks[zmin * NY];
            int p0 = max(0, min(NPTS - 64, pc - 32));
            scan(p0, p0 + 64);
            checkpoint();
        }
    }

    // Own rings with proper chord windows (covers phase-A window gaps;
    // duplicate candidates are harmless for a max). Then tighten bounds.
    for (int zr = zmin; zr <= zmax; zr++) scan_ring(zr);
    checkpoint();

    // Expansion outward with FROZEN bounds: stop at first unreachable ring
    // per side (dz lower bounds grow monotonically -> stop is final).
    for (int zr = zmin - 1; zr >= 0; zr--)
        if (!scan_ring(zr)) break;
    for (int zr = zmax + 1; zr < NZ; zr++)
        if (!scan_ring(zr)) break;

    checkpoint();  // final full maxima

    // Group term (uniform): sum_k (|s_k|^2 - 2*best_k).
    float term = 0.0f;
#pragma unroll
    for (int k = 0; k < GRP; k++) term += -2.0f * (sw[k] + mx[k]);

    unsigned last = 0;
    if (lane == 0) {
        g_csum[wg] = term;
        __threadfence();
        last = (atomicAdd(&g_count, 1) == TOTAL_WARPS - 1) ? 1u : 0u;
    }
    last = __shfl_sync(FULLM, last, 0);

    if (last) {
        __threadfence();  // acquire: all g_csum writes visible
        float acc = 0.0f;
#pragma unroll 8
        for (int kk = 0; kk < TOTAL_WARPS / 32; kk++)   // 256, fixed order
            acc += g_csum[lane + kk * 32];
#pragma unroll
        for (int off = 16; off > 0; off >>= 1)
            acc += __shfl_down_sync(FULLM, acc, off);
        if (lane == 0) {
            out[0] = acc * (1.0f / (float)BN);
            g_count = 0;  // reset for next graph replay
        }
    }
}

extern "C" void kernel_launch(void* const* d_in, const int* in_sizes, int n_in,
                              void* d_out, int out_size) {
    const float* f  = (const float*)d_in[0];
    const float* f_ = (const float*)d_in[1];
    float* out = (float*)d_out;

    build_kernel<<<16, 1024>>>(f, f_);        // 2 clouds x 8 batches
    nn_kernel<<<NN_BLOCKS, THREADS>>>(out);   // 1024 blocks x 256 threads
}